// round 15
// baseline (speedup 1.0000x reference)
#include <cuda_runtime.h>
#include <cuda_fp16.h>
#include <cstdint>
#include <math.h>

#define B_ 4
#define T_ 2048
#define C_ 1024
#define H_ 16
#define D_ 64

static const long long Y_ELEMS   = (long long)B_ * T_ * C_;        // 8,388,608
static const long long ATT_ELEMS = (long long)B_ * H_ * T_ * T_;   // 268,435,456

// exp2 argument scale folded into q: 0.125 * log2(e)
#define QSCALE 0.18033688011112043f

// Scratch (device globals; halves live inside reinterpreted float arrays)
__device__ float g_q[(size_t)B_ * H_ * T_ * D_ / 2];   // half, pre-scaled by QSCALE
__device__ float g_k[(size_t)B_ * H_ * T_ * D_ / 2];
__device__ float g_vT[(size_t)B_ * H_ * T_ * D_ / 2];  // half[B,H,D,T] token-pair-permuted
__device__ float g_yh[(size_t)B_ * T_ * C_ / 2];       // half[B*T*C] pair-permuted C
__device__ float g_att_fb[(size_t)B_ * H_ * T_ * T_];
__device__ float g_xr[(size_t)B_ * T_ * C_ / 2];       // half, pair-permuted k
__device__ float g_wqr[(size_t)C_ * C_ / 2];
__device__ float g_wkr[(size_t)C_ * C_ / 2];
__device__ float g_wvr[(size_t)C_ * C_ / 2];
__device__ float g_wpr[(size_t)C_ * C_ / 2];

// ---------------------------------------------------------------------------
// PTX helpers
// ---------------------------------------------------------------------------
__device__ __forceinline__ void mma_f16(float c[4],
                                        unsigned a0, unsigned a1, unsigned a2, unsigned a3,
                                        unsigned b0, unsigned b1) {
    asm volatile(
        "mma.sync.aligned.m16n8k16.row.col.f32.f16.f16.f32 "
        "{%0,%1,%2,%3},{%4,%5,%6,%7},{%8,%9},{%0,%1,%2,%3};\n"
        : "+f"(c[0]), "+f"(c[1]), "+f"(c[2]), "+f"(c[3])
        : "r"(a0), "r"(a1), "r"(a2), "r"(a3), "r"(b0), "r"(b1));
}

__device__ __forceinline__ float ex2f(float x) {
    float r;
    asm("ex2.approx.f32 %0, %1;" : "=f"(r) : "f"(x));
    return r;
}

__device__ __forceinline__ unsigned pack_h2(float lo, float hi) {
    __half2 h = __floats2half2_rn(lo, hi);
    return *(unsigned*)&h;
}

__device__ __forceinline__ void cp_async16(void* smem, const void* gmem) {
    uint32_t s = (uint32_t)__cvta_generic_to_shared(smem);
    asm volatile("cp.async.cg.shared.global [%0], [%1], 16;\n" :: "r"(s), "l"(gmem));
}
__device__ __forceinline__ void cp_commit() {
    asm volatile("cp.async.commit_group;\n");
}
template <int N>
__device__ __forceinline__ void cp_wait() {
    asm volatile("cp.async.wait_group %0;\n" :: "n"(N));
}

// pair-permutation: within each 16-half block, logical half2-pair j sits at
// position perm8(j). Fragment pairs (tig, tig+4) become adjacent -> LDS.64.
__device__ __host__ __forceinline__ int perm8(int j) {
    return ((j & 3) << 1) | ((j >> 2) & 1);
}
// token index -> permuted position (pairs of tokens within 16-token blocks)
__device__ __forceinline__ int tperm(int t) {
    return (t & ~15) | (perm8((t >> 1) & 7) << 1) | (t & 1);
}

#define PH 80   // smem pitch in halves (= 40 half2): frag words 8g+2tig, conflict-free

// ---------------------------------------------------------------------------
// Merged fp32 -> fp16 pair-perm rounding for x, Wq, Wk, Wv, Wp (one launch).
// ---------------------------------------------------------------------------
__global__ void round_half_perm_all(const float* __restrict__ x,
                                    const float* __restrict__ wq,
                                    const float* __restrict__ wk,
                                    const float* __restrict__ wv,
                                    const float* __restrict__ wp,
                                    __half* __restrict__ xo, __half* __restrict__ wqo,
                                    __half* __restrict__ wko, __half* __restrict__ wvo,
                                    __half* __restrict__ wpo)
{
    const int blk = blockIdx.x;
    const float* in; __half* out; int i;
    if (blk < 2048)      { in = x;  out = xo;  i = blk * 256 + threadIdx.x; }
    else if (blk < 2304) { in = wq; out = wqo; i = (blk - 2048) * 256 + threadIdx.x; }
    else if (blk < 2560) { in = wk; out = wko; i = (blk - 2304) * 256 + threadIdx.x; }
    else if (blk < 2816) { in = wv; out = wvo; i = (blk - 2560) * 256 + threadIdx.x; }
    else                 { in = wp; out = wpo; i = (blk - 2816) * 256 + threadIdx.x; }

    const float4* src = (const float4*)(in + (size_t)i * 16);
    float f[16];
    *(float4*)(f + 0)  = src[0];
    *(float4*)(f + 4)  = src[1];
    *(float4*)(f + 8)  = src[2];
    *(float4*)(f + 12) = src[3];
    __half2 b2[8];
#pragma unroll
    for (int j = 0; j < 8; j++)
        b2[perm8(j)] = __floats2half2_rn(f[2 * j], f[2 * j + 1]);
    uint4* o = (uint4*)(out + (size_t)i * 16);
    o[0] = ((uint4*)b2)[0];
    o[1] = ((uint4*)b2)[1];
}

// ---------------------------------------------------------------------------
// Dense GEMM: C = (A @ B^T + bias) * out_scale; A,B half, pair-permuted k.
// CTA 128x128, BK=64 halves, 2-stage cp.async, 2 CTAs/SM. 8 warps (4m x 2n),
// warp tile 32x64. All frag loads LDS.64.
// cmode: 0 fp32 dense out; 2 half scatter (B,H,T,D) pair-perm d (q,k);
//        3 half scatter transposed (B,H,D,T) token-perm (vT).
// ---------------------------------------------------------------------------
__device__ __forceinline__
void gemm_core(const __half* __restrict__ A, const __half* __restrict__ Bm,
               const float* __restrict__ bias, void* __restrict__ Cc,
               int N, int K, int cmode, float out_scale, __half2* sh)
{
    const int KC = K >> 6;                 // 64-half chunks
    __half2* As = sh;                      // [2][128][PH/2]
    __half2* Bs = sh + 2 * 128 * (PH / 2);

    const int tid  = threadIdx.x;
    const int warp = tid >> 5;
    const int lane = tid & 31;
    const int g    = lane >> 2;
    const int tig  = lane & 3;
    const int wm   = warp >> 1;
    const int wn   = warp & 1;

    const int m0 = blockIdx.y * 128;
    const int n0 = blockIdx.x * 128;
    const int lrow = tid >> 1;
    const int lo   = (tid & 1) * 32;       // halves

    float acc[2][8][4];
#pragma unroll
    for (int mi = 0; mi < 2; mi++)
#pragma unroll
        for (int ni = 0; ni < 8; ni++)
#pragma unroll
            for (int q = 0; q < 4; q++) acc[mi][ni][q] = 0.f;

    auto load_chunk = [&](int st, int kc) {
        const __half* Ag = A + (long long)(m0 + lrow) * K + kc * 64 + lo;
        __half* as = (__half*)(As + st * 128 * (PH / 2)) + lrow * PH + lo;
#pragma unroll
        for (int i = 0; i < 4; i++) cp_async16(as + i * 8, Ag + i * 8);
        const __half* Bg = Bm + (long long)(n0 + lrow) * K + kc * 64 + lo;
        __half* bs = (__half*)(Bs + st * 128 * (PH / 2)) + lrow * PH + lo;
#pragma unroll
        for (int i = 0; i < 4; i++) cp_async16(bs + i * 8, Bg + i * 8);
        cp_commit();
    };

    auto compute = [&](int st) {
        const __half2* au = As + st * 128 * (PH / 2) + (wm * 32) * (PH / 2);
        const __half2* bu = Bs + st * 128 * (PH / 2) + (wn * 64) * (PH / 2);
#pragma unroll
        for (int kb = 0; kb < 4; kb++) {
            const int ko = kb * 8 + 2 * tig;
            uint2 alo[2], ahi[2], bb[8];
#pragma unroll
            for (int mi = 0; mi < 2; mi++) {
                alo[mi] = *(const uint2*)(au + (mi * 16 + g) * (PH / 2) + ko);
                ahi[mi] = *(const uint2*)(au + (mi * 16 + g + 8) * (PH / 2) + ko);
            }
#pragma unroll
            for (int ni = 0; ni < 8; ni++)
                bb[ni] = *(const uint2*)(bu + (ni * 8 + g) * (PH / 2) + ko);
#pragma unroll
            for (int mi = 0; mi < 2; mi++)
#pragma unroll
                for (int ni = 0; ni < 8; ni++)
                    mma_f16(acc[mi][ni], alo[mi].x, ahi[mi].x, alo[mi].y, ahi[mi].y,
                            bb[ni].x, bb[ni].y);
        }
    };

    load_chunk(0, 0);
    for (int kc = 0; kc < KC; kc++) {
        cp_wait<0>();
        __syncthreads();
        if (kc + 1 < KC) load_chunk((kc + 1) & 1, kc + 1);
        compute(kc & 1);
    }

#pragma unroll
    for (int mi = 0; mi < 2; mi++) {
        const int r0 = m0 + wm * 32 + mi * 16 + g;
        const int r1 = r0 + 8;
#pragma unroll
        for (int ni = 0; ni < 8; ni++) {
            const int c = n0 + wn * 64 + ni * 8 + tig * 2;
            const float b0v = bias ? bias[c]     : 0.f;
            const float b1v = bias ? bias[c + 1] : 0.f;
            const float v00 = (acc[mi][ni][0] + b0v) * out_scale;
            const float v01 = (acc[mi][ni][1] + b1v) * out_scale;
            const float v10 = (acc[mi][ni][2] + b0v) * out_scale;
            const float v11 = (acc[mi][ni][3] + b1v) * out_scale;
            if (cmode == 0) {
                float* Co = (float*)Cc;
                *(float2*)&Co[(long long)r0 * N + c] = make_float2(v00, v01);
                *(float2*)&Co[(long long)r1 * N + c] = make_float2(v10, v11);
            } else {
                const int h  = c >> 6;
                const int dd = c & 63;
                const int b0i = r0 >> 11, t0 = r0 & 2047;
                const int b1i = r1 >> 11, t1 = r1 & 2047;
                __half* Ch = (__half*)Cc;
                if (cmode == 2) {
                    const int pos = (dd & ~15) | (perm8((dd >> 1) & 7) << 1);
                    __half* p0 = Ch + ((long long)(b0i * H_ + h) * T_ + t0) * D_;
                    __half* p1 = Ch + ((long long)(b1i * H_ + h) * T_ + t1) * D_;
                    *(__half2*)(p0 + pos) = __floats2half2_rn(v00, v01);
                    *(__half2*)(p1 + pos) = __floats2half2_rn(v10, v11);
                } else {   // cmode 3: vT[b,h,d,t'] scalar stores
                    const int tp0 = tperm(t0), tp1 = tperm(t1);
                    __half* base0 = Ch + ((long long)(b0i * H_ + h) * D_ + dd) * T_;
                    __half* base1 = Ch + ((long long)(b1i * H_ + h) * D_ + dd) * T_;
                    base0[tp0]      = __float2half_rn(v00);
                    base0[T_ + tp0] = __float2half_rn(v01);   // dd+1 row
                    base1[tp1]      = __float2half_rn(v10);
                    base1[T_ + tp1] = __float2half_rn(v11);
                }
            }
        }
    }
}

__global__ __launch_bounds__(256, 2)
void qkv_gemm(const __half* __restrict__ xr,
              const __half* __restrict__ wq, const __half* __restrict__ wk,
              const __half* __restrict__ wv,
              const float* __restrict__ bq, const float* __restrict__ bk,
              const float* __restrict__ bv,
              __half* __restrict__ q, __half* __restrict__ k, __half* __restrict__ vT)
{
    extern __shared__ __half2 sh2[];
    if (blockIdx.z == 0)      gemm_core(xr, wq, bq, q,  C_, C_, 2, QSCALE, sh2);
    else if (blockIdx.z == 1) gemm_core(xr, wk, bk, k,  C_, C_, 2, 1.f, sh2);
    else                      gemm_core(xr, wv, bv, vT, C_, C_, 3, 1.f, sh2);
}

__global__ __launch_bounds__(256, 2)
void proj_gemm(const __half* __restrict__ A, const __half* __restrict__ Bm,
               const float* __restrict__ bias, float* __restrict__ Cc)
{
    extern __shared__ __half2 sh2[];
    gemm_core(A, Bm, bias, Cc, C_, C_, 0, 1.f, sh2);
}

// ---------------------------------------------------------------------------
// Two-pass flash attention, fp16 mma, 3-stage cp.async pipeline (wait<1>).
// Per CTA: 128 query rows x one head. Q pre-scaled by 0.125*log2e -> ex2.
// 8 warps x 16 rows. P@V register-direct from the QK^T C-fragments.
// smem: Qs[128][PH], Ks[3][64][PH], Vs[3][64][PH] halves + Ms[3][64] f32
//       = 82,688 B -> 2 CTAs/SM.
// ---------------------------------------------------------------------------
__global__ __launch_bounds__(256, 2)
void flash_att(const __half* __restrict__ q, const __half* __restrict__ k,
               const __half* __restrict__ vT, const float* __restrict__ mask,
               float* __restrict__ att, __half* __restrict__ Y)
{
    const int z = blockIdx.z;
    const int b = z >> 4, h = z & 15;
    const int m0 = blockIdx.y * 128;
    const __half* Qg = q  + (long long)z * T_ * D_;
    const __half* Kg = k  + (long long)z * T_ * D_;
    const __half* Vg = vT + (long long)z * T_ * D_;   // [D][T] per (b,h)
    float* Sg = att + (long long)z * T_ * T_;
    const float* mrow = mask + (long long)b * T_;

    extern __shared__ __half2 sh2[];
    __half2* Qs = sh2;                         // 128*(PH/2)
    __half2* Ks = Qs + 128 * (PH / 2);         // 3*64*(PH/2)
    __half2* Vs = Ks + 3 * 64 * (PH / 2);      // 3*64*(PH/2)
    float*   Ms = (float*)(Vs + 3 * 64 * (PH / 2));   // 3*64 f32

    const int tid  = threadIdx.x;
    const int warp = tid >> 5;
    const int lane = tid & 31;
    const int g    = lane >> 2;
    const int tig  = lane & 3;

    // Q load (once): 128 rows x 64 halves
    {
        const int row = tid >> 1;
        const int off = (tid & 1) * 32;
        const __half* src = Qg + (long long)(m0 + row) * D_ + off;
        __half* dst = (__half*)Qs + row * PH + off;
#pragma unroll
        for (int i = 0; i < 4; i++) cp_async16(dst + i * 8, src + i * 8);
        cp_commit();
    }

    const int krow = tid >> 2;                 // 0..63
    const int koff = (tid & 3) * 16;           // halves

    auto load_k = [&](int st, int kc) {
        const __half* src = Kg + (long long)(kc * 64 + krow) * D_ + koff;
        __half* dst = (__half*)(Ks + st * 64 * (PH / 2)) + krow * PH + koff;
        cp_async16(dst, src);
        cp_async16(dst + 8, src + 8);
    };
    auto load_v = [&](int st, int kc) {
        const __half* src = Vg + (long long)krow * T_ + kc * 64 + koff;
        __half* dst = (__half*)(Vs + st * 64 * (PH / 2)) + krow * PH + koff;
        cp_async16(dst, src);
        cp_async16(dst + 8, src + 8);
    };
    auto load_m = [&](int st, int kc) {
        if (tid < 16) cp_async16(Ms + st * 64 + tid * 4, mrow + kc * 64 + tid * 4);
    };

    // QK^T: warp 16 rows x 64 keys, k = 64 d (4 k16-blocks)
    float sacc[8][4];
    auto smma = [&](int st) {
#pragma unroll
        for (int ni = 0; ni < 8; ni++)
#pragma unroll
            for (int qq = 0; qq < 4; qq++) sacc[ni][qq] = 0.f;
        const __half2* au = Qs + (warp * 16) * (PH / 2);
        const __half2* bu = Ks + st * 64 * (PH / 2);
#pragma unroll
        for (int kb = 0; kb < 4; kb++) {
            const int ko = kb * 8 + 2 * tig;
            const uint2 alo = *(const uint2*)(au + g * (PH / 2) + ko);
            const uint2 ahi = *(const uint2*)(au + (g + 8) * (PH / 2) + ko);
            uint2 bb[8];
#pragma unroll
            for (int ni = 0; ni < 8; ni++)
                bb[ni] = *(const uint2*)(bu + (ni * 8 + g) * (PH / 2) + ko);
#pragma unroll
            for (int ni = 0; ni < 8; ni++)
                mma_f16(sacc[ni], alo.x, ahi.x, alo.y, ahi.y, bb[ni].x, bb[ni].y);
        }
    };

    const int NC = T_ / 64;   // 32 chunks

    // ------------------ Pass A: exp2-sum (registers only), 3-stage --------
    float rsum0 = 0.f, rsum1 = 0.f;
    load_k(0, 0); cp_commit();
    load_k(1, 1); cp_commit();
    for (int kc = 0; kc < NC; kc++) {
        cp_wait<1>();
        __syncthreads();
        if (kc + 2 < NC) { load_k((kc + 2) % 3, kc + 2); cp_commit(); }
        smma(kc % 3);
#pragma unroll
        for (int ni = 0; ni < 8; ni++) {
            rsum0 += ex2f(sacc[ni][0]) + ex2f(sacc[ni][1]);
            rsum1 += ex2f(sacc[ni][2]) + ex2f(sacc[ni][3]);
        }
    }
    rsum0 += __shfl_xor_sync(0xffffffffu, rsum0, 1);
    rsum0 += __shfl_xor_sync(0xffffffffu, rsum0, 2);
    rsum1 += __shfl_xor_sync(0xffffffffu, rsum1, 1);
    rsum1 += __shfl_xor_sync(0xffffffffu, rsum1, 2);
    const float il0 = 1.f / rsum0;
    const float il1 = 1.f / rsum1;

    // All warps must be done with pass A's last K stages before pass B
    // prologue overwrites them.
    __syncthreads();

    // ------------------ Pass B: att write + register-direct P@V, 3-stage --
    float yacc[8][4];
#pragma unroll
    for (int ni = 0; ni < 8; ni++) {
        yacc[ni][0] = 0.f; yacc[ni][1] = 0.f;
        yacc[ni][2] = 0.f; yacc[ni][3] = 0.f;
    }

    const int r0 = m0 + warp * 16 + g;
    const int r1 = r0 + 8;

    load_k(0, 0); load_v(0, 0); load_m(0, 0); cp_commit();
    load_k(1, 1); load_v(1, 1); load_m(1, 1); cp_commit();
    for (int kc = 0; kc < NC; kc++) {
        cp_wait<1>();
        __syncthreads();
        if (kc + 2 < NC) {
            const int st = (kc + 2) % 3;
            load_k(st, kc + 2); load_v(st, kc + 2); load_m(st, kc + 2);
            cp_commit();
        }
        const int st = kc % 3;
        smma(st);

        const __half2* vb = Vs + st * 64 * (PH / 2);
        const float* mp = Ms + st * 64;
#pragma unroll
        for (int kb = 0; kb < 4; kb++) {
            // two adjacent 8-key C-tiles = one m16n8k16 A fragment
            const int cl0 = kb * 16 + tig * 2;
            const int cl1 = cl0 + 8;
            const float mk00 = mp[cl0];
            const float mk01 = mp[cl0 + 1];
            const float mk10 = mp[cl1];
            const float mk11 = mp[cl1 + 1];
            const float p00 = ex2f(sacc[2 * kb][0]) * il0 * mk00;
            const float p01 = ex2f(sacc[2 * kb][1]) * il0 * mk01;
            const float p10 = ex2f(sacc[2 * kb][2]) * il1 * mk00;
            const float p11 = ex2f(sacc[2 * kb][3]) * il1 * mk01;
            const float q00 = ex2f(sacc[2 * kb + 1][0]) * il0 * mk10;
            const float q01 = ex2f(sacc[2 * kb + 1][1]) * il0 * mk11;
            const float q10 = ex2f(sacc[2 * kb + 1][2]) * il1 * mk10;
            const float q11 = ex2f(sacc[2 * kb + 1][3]) * il1 * mk11;
            const unsigned a0 = pack_h2(p00, p01);
            const unsigned a1 = pack_h2(p10, p11);
            const unsigned a2 = pack_h2(q00, q01);
            const unsigned a3 = pack_h2(q10, q11);
            const int ko = kb * 8 + 2 * tig;
            // issue mma first (tensor pipe), stores after (independent)
#pragma unroll
            for (int nc = 0; nc < 8; nc++) {
                const uint2 bb = *(const uint2*)(vb + (nc * 8 + g) * (PH / 2) + ko);
                mma_f16(yacc[nc], a0, a1, a2, a3, bb.x, bb.y);
            }
            const long long gc0 = (long long)kc * 64 + cl0;
            const long long gc1 = (long long)kc * 64 + cl1;
            __stcs((float2*)&Sg[(long long)r0 * T_ + gc0], make_float2(p00, p01));
            __stcs((float2*)&Sg[(long long)r1 * T_ + gc0], make_float2(p10, p11));
            __stcs((float2*)&Sg[(long long)r0 * T_ + gc1], make_float2(q00, q01));
            __stcs((float2*)&Sg[(long long)r1 * T_ + gc1], make_float2(q10, q11));
        }
    }

    // write Y (half, pair-permuted within each 16 of C) for the proj GEMM
    {
#pragma unroll
        for (int nc = 0; nc < 8; nc++) {
            const int dd = nc * 8 + tig * 2;
            const int pos = h * D_ + ((dd & ~15) | (perm8((dd >> 1) & 7) << 1));
            __half* p0 = Y + (long long)(b * T_ + r0) * C_;
            __half* p1 = Y + (long long)(b * T_ + r1) * C_;
            *(__half2*)(p0 + pos) = __floats2half2_rn(yacc[nc][0], yacc[nc][1]);
            *(__half2*)(p1 + pos) = __floats2half2_rn(yacc[nc][2], yacc[nc][3]);
        }
    }
}

// ---------------------------------------------------------------------------
// Launch
// ---------------------------------------------------------------------------
extern "C" void kernel_launch(void* const* d_in, const int* in_sizes, int n_in,
                              void* d_out, int out_size)
{
    const float* x    = (const float*)d_in[0];
    const float* mask = (const float*)d_in[2];
    const float* Wq   = (const float*)d_in[3];
    const float* bq   = (const float*)d_in[4];
    const float* Wk   = (const float*)d_in[5];
    const float* bk   = (const float*)d_in[6];
    const float* Wv   = (const float*)d_in[7];
    const float* bv   = (const float*)d_in[8];
    const float* Wp   = (const float*)d_in[9];
    const float* bp   = (const float*)d_in[10];
    float* out = (float*)d_out;

    float *pq, *pk, *pvT, *py, *patt_fb, *pxr, *pwq, *pwk, *pwv, *pwp;
    cudaGetSymbolAddress((void**)&pq, g_q);
    cudaGetSymbolAddress((void**)&pk, g_k);
    cudaGetSymbolAddress((void**)&pvT, g_vT);
    cudaGetSymbolAddress((void**)&py, g_yh);
    cudaGetSymbolAddress((void**)&patt_fb, g_att_fb);
    cudaGetSymbolAddress((void**)&pxr, g_xr);
    cudaGetSymbolAddress((void**)&pwq, g_wqr);
    cudaGetSymbolAddress((void**)&pwk, g_wkr);
    cudaGetSymbolAddress((void**)&pwv, g_wvr);
    cudaGetSymbolAddress((void**)&pwp, g_wpr);

    float* yout;
    float* att;
    if ((long long)out_size >= Y_ELEMS + ATT_ELEMS) {
        yout = out;  att = out + Y_ELEMS;
    } else if ((long long)out_size == ATT_ELEMS) {
        yout = nullptr;  att = out;
    } else {
        yout = out;  att = patt_fb;
    }

    const int GEMM_SMEM  = 2 * 2 * 128 * PH * 2;                    // 81,920 B
    const int FLASH_SMEM = (128 + 3 * 64 + 3 * 64) * PH * 2 + 3 * 64 * 4; // 82,688 B
    cudaFuncSetAttribute(qkv_gemm,  cudaFuncAttributeMaxDynamicSharedMemorySize, GEMM_SMEM);
    cudaFuncSetAttribute(proj_gemm, cudaFuncAttributeMaxDynamicSharedMemorySize, GEMM_SMEM);
    cudaFuncSetAttribute(flash_att, cudaFuncAttributeMaxDynamicSharedMemorySize, FLASH_SMEM);

    const dim3 blk(256);

    // 0) one merged fp32 -> fp16 pair-perm rounding launch (x + 4 weights)
    round_half_perm_all<<<3072, 256>>>(x, Wq, Wk, Wv, Wp,
                                       (__half*)pxr, (__half*)pwq, (__half*)pwk,
                                       (__half*)pwv, (__half*)pwp);

    // 1) merged Q/K/V projections (q scaled by QSCALE; v transposed+token-perm)
    qkv_gemm<<<dim3(C_ / 128, (B_ * T_) / 128, 3), blk, GEMM_SMEM>>>(
        (const __half*)pxr, (const __half*)pwq, (const __half*)pwk, (const __half*)pwv,
        bq, bk, bv, (__half*)pq, (__half*)pk, (__half*)pvT);

    // 2) fused two-pass flash attention: att (fp32, written once) + Y (half)
    flash_att<<<dim3(1, T_ / 128, B_ * H_), blk, FLASH_SMEM>>>(
        (const __half*)pq, (const __half*)pk, (const __half*)pvT, mask, att, (__half*)py);

    // 3) output projection (fp32 out + bias)
    if (yout)
        proj_gemm<<<dim3(C_ / 128, (B_ * T_) / 128, 1), blk, GEMM_SMEM>>>(
            (const __half*)py, (const __half*)pwp, bp, yout);
}

// round 17
// speedup vs baseline: 1.0184x; 1.0184x over previous
#include <cuda_runtime.h>
#include <cuda_fp16.h>
#include <cstdint>
#include <math.h>

#define B_ 4
#define T_ 2048
#define C_ 1024
#define H_ 16
#define D_ 64

static const long long Y_ELEMS   = (long long)B_ * T_ * C_;        // 8,388,608
static const long long ATT_ELEMS = (long long)B_ * H_ * T_ * T_;   // 268,435,456

// exp2 argument scale folded into q: 0.125 * log2(e)
#define QSCALE 0.18033688011112043f

// Scratch (device globals; halves live inside reinterpreted float arrays)
__device__ float g_q[(size_t)B_ * H_ * T_ * D_ / 2];   // half, pre-scaled by QSCALE
__device__ float g_k[(size_t)B_ * H_ * T_ * D_ / 2];
__device__ float g_vT[(size_t)B_ * H_ * T_ * D_ / 2];  // half[B,H,D,T] token-pair-permuted
__device__ float g_yh[(size_t)B_ * T_ * C_ / 2];       // half[B*T*C] pair-permuted C
__device__ float g_att_fb[(size_t)B_ * H_ * T_ * T_];
__device__ float g_xr[(size_t)B_ * T_ * C_ / 2];       // half, pair-permuted k
__device__ float g_wqr[(size_t)C_ * C_ / 2];
__device__ float g_wkr[(size_t)C_ * C_ / 2];
__device__ float g_wvr[(size_t)C_ * C_ / 2];
__device__ float g_wpr[(size_t)C_ * C_ / 2];
__device__ float g_maskh[(size_t)B_ * T_ / 2];         // half[B][T]

// ---------------------------------------------------------------------------
// PTX helpers
// ---------------------------------------------------------------------------
__device__ __forceinline__ void mma_f16(float c[4],
                                        unsigned a0, unsigned a1, unsigned a2, unsigned a3,
                                        unsigned b0, unsigned b1) {
    asm volatile(
        "mma.sync.aligned.m16n8k16.row.col.f32.f16.f16.f32 "
        "{%0,%1,%2,%3},{%4,%5,%6,%7},{%8,%9},{%0,%1,%2,%3};\n"
        : "+f"(c[0]), "+f"(c[1]), "+f"(c[2]), "+f"(c[3])
        : "r"(a0), "r"(a1), "r"(a2), "r"(a3), "r"(b0), "r"(b1));
}

// two exps in one MUFU op
__device__ __forceinline__ unsigned h2ex2(unsigned x) {
    unsigned r;
    asm("ex2.approx.f16x2 %0, %1;" : "=r"(r) : "r"(x));
    return r;
}

__device__ __forceinline__ unsigned pack_h2(float lo, float hi) {
    __half2 h = __floats2half2_rn(lo, hi);
    return *(unsigned*)&h;
}
__device__ __forceinline__ unsigned hmul2u(unsigned a, unsigned b) {
    __half2 r = __hmul2(*(__half2*)&a, *(__half2*)&b);
    return *(unsigned*)&r;
}
__device__ __forceinline__ float2 h2f2(unsigned a) {
    return __half22float2(*(__half2*)&a);
}

__device__ __forceinline__ void cp_async16(void* smem, const void* gmem) {
    uint32_t s = (uint32_t)__cvta_generic_to_shared(smem);
    asm volatile("cp.async.cg.shared.global [%0], [%1], 16;\n" :: "r"(s), "l"(gmem));
}
__device__ __forceinline__ void cp_commit() {
    asm volatile("cp.async.commit_group;\n");
}
template <int N>
__device__ __forceinline__ void cp_wait() {
    asm volatile("cp.async.wait_group %0;\n" :: "n"(N));
}

// pair-permutation: within each 16-half block, logical half2-pair j sits at
// position perm8(j). Fragment pairs (tig, tig+4) become adjacent -> LDS.64.
__device__ __host__ __forceinline__ int perm8(int j) {
    return ((j & 3) << 1) | ((j >> 2) & 1);
}
// token index -> permuted position (pairs of tokens within 16-token blocks)
__device__ __forceinline__ int tperm(int t) {
    return (t & ~15) | (perm8((t >> 1) & 7) << 1) | (t & 1);
}

#define PH 80           // smem pitch in halves: frag words conflict-free
#define ONES2 0x3C003C00u   // half2(1,1)

// ---------------------------------------------------------------------------
// Merged fp32 -> fp16 rounding: x/Wq/Wk/Wv/Wp pair-permuted; mask natural.
// Grid 3074: x [0,2048), Wq..Wp 256 each [2048,3072), mask [3072,3074).
// ---------------------------------------------------------------------------
__global__ void round_half_perm_all(const float* __restrict__ x,
                                    const float* __restrict__ wq,
                                    const float* __restrict__ wk,
                                    const float* __restrict__ wv,
                                    const float* __restrict__ wp,
                                    const float* __restrict__ mask,
                                    __half* __restrict__ xo, __half* __restrict__ wqo,
                                    __half* __restrict__ wko, __half* __restrict__ wvo,
                                    __half* __restrict__ wpo, __half* __restrict__ mo)
{
    const int blk = blockIdx.x;
    if (blk >= 3072) {   // mask: natural order conversion
        const int i = (blk - 3072) * 256 + threadIdx.x;   // 0..511
        const float4* src = (const float4*)(mask + (size_t)i * 16);
        float f[16];
        *(float4*)(f + 0)  = src[0];
        *(float4*)(f + 4)  = src[1];
        *(float4*)(f + 8)  = src[2];
        *(float4*)(f + 12) = src[3];
        __half2 b2[8];
#pragma unroll
        for (int j = 0; j < 8; j++)
            b2[j] = __floats2half2_rn(f[2 * j], f[2 * j + 1]);
        uint4* o = (uint4*)(mo + (size_t)i * 16);
        o[0] = ((uint4*)b2)[0];
        o[1] = ((uint4*)b2)[1];
        return;
    }
    const float* in; __half* out; int i;
    if (blk < 2048)      { in = x;  out = xo;  i = blk * 256 + threadIdx.x; }
    else if (blk < 2304) { in = wq; out = wqo; i = (blk - 2048) * 256 + threadIdx.x; }
    else if (blk < 2560) { in = wk; out = wko; i = (blk - 2304) * 256 + threadIdx.x; }
    else if (blk < 2816) { in = wv; out = wvo; i = (blk - 2560) * 256 + threadIdx.x; }
    else                 { in = wp; out = wpo; i = (blk - 2816) * 256 + threadIdx.x; }

    const float4* src = (const float4*)(in + (size_t)i * 16);
    float f[16];
    *(float4*)(f + 0)  = src[0];
    *(float4*)(f + 4)  = src[1];
    *(float4*)(f + 8)  = src[2];
    *(float4*)(f + 12) = src[3];
    __half2 b2[8];
#pragma unroll
    for (int j = 0; j < 8; j++)
        b2[perm8(j)] = __floats2half2_rn(f[2 * j], f[2 * j + 1]);
    uint4* o = (uint4*)(out + (size_t)i * 16);
    o[0] = ((uint4*)b2)[0];
    o[1] = ((uint4*)b2)[1];
}

// ---------------------------------------------------------------------------
// Dense GEMM: C = (A @ B^T + bias) * out_scale; A,B half, pair-permuted k.
// CTA 128x128, BK=64 halves, 2-stage cp.async, 2 CTAs/SM. 8 warps (4m x 2n),
// warp tile 32x64. All frag loads LDS.64.
// cmode: 0 fp32 dense out; 2 half scatter (B,H,T,D) pair-perm d (q,k);
//        3 half scatter transposed (B,H,D,T) token-perm (vT).
// ---------------------------------------------------------------------------
__device__ __forceinline__
void gemm_core(const __half* __restrict__ A, const __half* __restrict__ Bm,
               const float* __restrict__ bias, void* __restrict__ Cc,
               int N, int K, int cmode, float out_scale, __half2* sh)
{
    const int KC = K >> 6;                 // 64-half chunks
    __half2* As = sh;                      // [2][128][PH/2]
    __half2* Bs = sh + 2 * 128 * (PH / 2);

    const int tid  = threadIdx.x;
    const int warp = tid >> 5;
    const int lane = tid & 31;
    const int g    = lane >> 2;
    const int tig  = lane & 3;
    const int wm   = warp >> 1;
    const int wn   = warp & 1;

    const int m0 = blockIdx.y * 128;
    const int n0 = blockIdx.x * 128;
    const int lrow = tid >> 1;
    const int lo   = (tid & 1) * 32;       // halves

    float acc[2][8][4];
#pragma unroll
    for (int mi = 0; mi < 2; mi++)
#pragma unroll
        for (int ni = 0; ni < 8; ni++)
#pragma unroll
            for (int q = 0; q < 4; q++) acc[mi][ni][q] = 0.f;

    auto load_chunk = [&](int st, int kc) {
        const __half* Ag = A + (long long)(m0 + lrow) * K + kc * 64 + lo;
        __half* as = (__half*)(As + st * 128 * (PH / 2)) + lrow * PH + lo;
#pragma unroll
        for (int i = 0; i < 4; i++) cp_async16(as + i * 8, Ag + i * 8);
        const __half* Bg = Bm + (long long)(n0 + lrow) * K + kc * 64 + lo;
        __half* bs = (__half*)(Bs + st * 128 * (PH / 2)) + lrow * PH + lo;
#pragma unroll
        for (int i = 0; i < 4; i++) cp_async16(bs + i * 8, Bg + i * 8);
        cp_commit();
    };

    auto compute = [&](int st) {
        const __half2* au = As + st * 128 * (PH / 2) + (wm * 32) * (PH / 2);
        const __half2* bu = Bs + st * 128 * (PH / 2) + (wn * 64) * (PH / 2);
#pragma unroll
        for (int kb = 0; kb < 4; kb++) {
            const int ko = kb * 8 + 2 * tig;
            uint2 alo[2], ahi[2], bb[8];
#pragma unroll
            for (int mi = 0; mi < 2; mi++) {
                alo[mi] = *(const uint2*)(au + (mi * 16 + g) * (PH / 2) + ko);
                ahi[mi] = *(const uint2*)(au + (mi * 16 + g + 8) * (PH / 2) + ko);
            }
#pragma unroll
            for (int ni = 0; ni < 8; ni++)
                bb[ni] = *(const uint2*)(bu + (ni * 8 + g) * (PH / 2) + ko);
#pragma unroll
            for (int mi = 0; mi < 2; mi++)
#pragma unroll
                for (int ni = 0; ni < 8; ni++)
                    mma_f16(acc[mi][ni], alo[mi].x, ahi[mi].x, alo[mi].y, ahi[mi].y,
                            bb[ni].x, bb[ni].y);
        }
    };

    load_chunk(0, 0);
    for (int kc = 0; kc < KC; kc++) {
        cp_wait<0>();
        __syncthreads();
        if (kc + 1 < KC) load_chunk((kc + 1) & 1, kc + 1);
        compute(kc & 1);
    }

#pragma unroll
    for (int mi = 0; mi < 2; mi++) {
        const int r0 = m0 + wm * 32 + mi * 16 + g;
        const int r1 = r0 + 8;
#pragma unroll
        for (int ni = 0; ni < 8; ni++) {
            const int c = n0 + wn * 64 + ni * 8 + tig * 2;
            const float b0v = bias ? bias[c]     : 0.f;
            const float b1v = bias ? bias[c + 1] : 0.f;
            const float v00 = (acc[mi][ni][0] + b0v) * out_scale;
            const float v01 = (acc[mi][ni][1] + b1v) * out_scale;
            const float v10 = (acc[mi][ni][2] + b0v) * out_scale;
            const float v11 = (acc[mi][ni][3] + b1v) * out_scale;
            if (cmode == 0) {
                float* Co = (float*)Cc;
                *(float2*)&Co[(long long)r0 * N + c] = make_float2(v00, v01);
                *(float2*)&Co[(long long)r1 * N + c] = make_float2(v10, v11);
            } else {
                const int h  = c >> 6;
                const int dd = c & 63;
                const int b0i = r0 >> 11, t0 = r0 & 2047;
                const int b1i = r1 >> 11, t1 = r1 & 2047;
                __half* Ch = (__half*)Cc;
                if (cmode == 2) {
                    const int pos = (dd & ~15) | (perm8((dd >> 1) & 7) << 1);
                    __half* p0 = Ch + ((long long)(b0i * H_ + h) * T_ + t0) * D_;
                    __half* p1 = Ch + ((long long)(b1i * H_ + h) * T_ + t1) * D_;
                    *(__half2*)(p0 + pos) = __floats2half2_rn(v00, v01);
                    *(__half2*)(p1 + pos) = __floats2half2_rn(v10, v11);
                } else {   // cmode 3: vT[b,h,d,t'] scalar stores
                    const int tp0 = tperm(t0), tp1 = tperm(t1);
                    __half* base0 = Ch + ((long long)(b0i * H_ + h) * D_ + dd) * T_;
                    __half* base1 = Ch + ((long long)(b1i * H_ + h) * D_ + dd) * T_;
                    base0[tp0]      = __float2half_rn(v00);
                    base0[T_ + tp0] = __float2half_rn(v01);   // dd+1 row
                    base1[tp1]      = __float2half_rn(v10);
                    base1[T_ + tp1] = __float2half_rn(v11);
                }
            }
        }
    }
}

__global__ __launch_bounds__(256, 2)
void qkv_gemm(const __half* __restrict__ xr,
              const __half* __restrict__ wq, const __half* __restrict__ wk,
              const __half* __restrict__ wv,
              const float* __restrict__ bq, const float* __restrict__ bk,
              const float* __restrict__ bv,
              __half* __restrict__ q, __half* __restrict__ k, __half* __restrict__ vT)
{
    extern __shared__ __half2 sh2[];
    if (blockIdx.z == 0)      gemm_core(xr, wq, bq, q,  C_, C_, 2, QSCALE, sh2);
    else if (blockIdx.z == 1) gemm_core(xr, wk, bk, k,  C_, C_, 2, 1.f, sh2);
    else                      gemm_core(xr, wv, bv, vT, C_, C_, 3, 1.f, sh2);
}

__global__ __launch_bounds__(256, 2)
void proj_gemm(const __half* __restrict__ A, const __half* __restrict__ Bm,
               const float* __restrict__ bias, float* __restrict__ Cc)
{
    extern __shared__ __half2 sh2[];
    gemm_core(A, Bm, bias, Cc, C_, C_, 0, 1.f, sh2);
}

// ---------------------------------------------------------------------------
// Two-pass flash attention, fp16 mma + f16x2 exp (half the MUFU ops).
// Pass A: QK^T, p=h2ex2(s), row-sums via mma against all-ones B (fp32 acc,
//         every lane ends with its rows' totals -> no shuffles).
// Pass B: recompute, A-frags = h2ex2(s)*il*mask in half2; att store = same
//         values cvt to f32; register-direct P@V.
// smem: Qs[128][PH], Ks[2][64][PH], Vs[2][64][PH] halves + Msh[2][64] halves
// ---------------------------------------------------------------------------
__global__ __launch_bounds__(256, 2)
void flash_att(const __half* __restrict__ q, const __half* __restrict__ k,
               const __half* __restrict__ vT, const __half* __restrict__ maskh,
               float* __restrict__ att, __half* __restrict__ Y)
{
    const int z = blockIdx.z;
    const int b = z >> 4, h = z & 15;
    const int m0 = blockIdx.y * 128;
    const __half* Qg = q  + (long long)z * T_ * D_;
    const __half* Kg = k  + (long long)z * T_ * D_;
    const __half* Vg = vT + (long long)z * T_ * D_;   // [D][T] per (b,h)
    float* Sg = att + (long long)z * T_ * T_;
    const __half* mrow = maskh + (long long)b * T_;

    extern __shared__ __half2 sh2[];
    __half2* Qs  = sh2;                        // 128*(PH/2)
    __half2* Ks  = Qs + 128 * (PH / 2);        // 2*64*(PH/2)
    __half2* Vs  = Ks + 2 * 64 * (PH / 2);     // 2*64*(PH/2)
    __half2* Msh = Vs + 2 * 64 * (PH / 2);     // 2*32 half2

    const int tid  = threadIdx.x;
    const int warp = tid >> 5;
    const int lane = tid & 31;
    const int g    = lane >> 2;
    const int tig  = lane & 3;

    // Q load (once): 128 rows x 64 halves
    {
        const int row = tid >> 1;
        const int off = (tid & 1) * 32;
        const __half* src = Qg + (long long)(m0 + row) * D_ + off;
        __half* dst = (__half*)Qs + row * PH + off;
#pragma unroll
        for (int i = 0; i < 4; i++) cp_async16(dst + i * 8, src + i * 8);
        cp_commit();
    }

    const int krow = tid >> 2;                 // 0..63
    const int koff = (tid & 3) * 16;           // halves

    auto load_k = [&](int st, int kc) {
        const __half* src = Kg + (long long)(kc * 64 + krow) * D_ + koff;
        __half* dst = (__half*)(Ks + st * 64 * (PH / 2)) + krow * PH + koff;
        cp_async16(dst, src);
        cp_async16(dst + 8, src + 8);
    };
    auto load_v = [&](int st, int kc) {
        const __half* src = Vg + (long long)krow * T_ + kc * 64 + koff;
        __half* dst = (__half*)(Vs + st * 64 * (PH / 2)) + krow * PH + koff;
        cp_async16(dst, src);
        cp_async16(dst + 8, src + 8);
    };
    auto load_m = [&](int st, int kc) {
        if (tid < 8)
            cp_async16((__half*)(Msh + st * 32) + tid * 8, mrow + kc * 64 + tid * 8);
    };

    // QK^T: warp 16 rows x 64 keys, k = 64 d (4 k16-blocks)
    float sacc[8][4];
    auto smma = [&](int st) {
#pragma unroll
        for (int ni = 0; ni < 8; ni++)
#pragma unroll
            for (int qq = 0; qq < 4; qq++) sacc[ni][qq] = 0.f;
        const __half2* au = Qs + (warp * 16) * (PH / 2);
        const __half2* bu = Ks + st * 64 * (PH / 2);
#pragma unroll
        for (int kb = 0; kb < 4; kb++) {
            const int ko = kb * 8 + 2 * tig;
            const uint2 alo = *(const uint2*)(au + g * (PH / 2) + ko);
            const uint2 ahi = *(const uint2*)(au + (g + 8) * (PH / 2) + ko);
            uint2 bb[8];
#pragma unroll
            for (int ni = 0; ni < 8; ni++)
                bb[ni] = *(const uint2*)(bu + (ni * 8 + g) * (PH / 2) + ko);
#pragma unroll
            for (int ni = 0; ni < 8; ni++)
                mma_f16(sacc[ni], alo.x, ahi.x, alo.y, ahi.y, bb[ni].x, bb[ni].y);
        }
    };

    const int NC = T_ / 64;   // 32 chunks

    // ---- Pass A: row sums of exp via ones-mma (MUFU halved, no shuffles) --
    float sumacc[4] = {0.f, 0.f, 0.f, 0.f};
    load_k(0, 0); cp_commit();
    for (int kc = 0; kc < NC; kc++) {
        cp_wait<0>();
        __syncthreads();
        if (kc + 1 < NC) { load_k((kc + 1) & 1, kc + 1); cp_commit(); }
        smma(kc & 1);
#pragma unroll
        for (int kb = 0; kb < 4; kb++) {
            const unsigned a0 = h2ex2(pack_h2(sacc[2 * kb][0],     sacc[2 * kb][1]));
            const unsigned a1 = h2ex2(pack_h2(sacc[2 * kb][2],     sacc[2 * kb][3]));
            const unsigned a2 = h2ex2(pack_h2(sacc[2 * kb + 1][0], sacc[2 * kb + 1][1]));
            const unsigned a3 = h2ex2(pack_h2(sacc[2 * kb + 1][2], sacc[2 * kb + 1][3]));
            mma_f16(sumacc, a0, a1, a2, a3, ONES2, ONES2);
        }
    }
    const float il0 = 1.f / sumacc[0];   // row r0 total (all lanes identical)
    const float il1 = 1.f / sumacc[2];   // row r1 total
    const unsigned il0h = pack_h2(il0, il0);
    const unsigned il1h = pack_h2(il1, il1);

    __syncthreads();   // pass A's last K stage vs pass B prologue overwrite

    // ---- Pass B: att write + register-direct P@V ----
    float yacc[8][4];
#pragma unroll
    for (int ni = 0; ni < 8; ni++) {
        yacc[ni][0] = 0.f; yacc[ni][1] = 0.f;
        yacc[ni][2] = 0.f; yacc[ni][3] = 0.f;
    }

    const int r0 = m0 + warp * 16 + g;
    const int r1 = r0 + 8;

    load_k(0, 0); load_v(0, 0); load_m(0, 0); cp_commit();
    for (int kc = 0; kc < NC; kc++) {
        cp_wait<0>();
        __syncthreads();
        if (kc + 1 < NC) {
            const int st = (kc + 1) & 1;
            load_k(st, kc + 1); load_v(st, kc + 1); load_m(st, kc + 1);
            cp_commit();
        }
        const int st = kc & 1;
        smma(st);

        const __half2* vb = Vs + st * 64 * (PH / 2);
#pragma unroll
        for (int kb = 0; kb < 4; kb++) {
            const int cl0 = kb * 16 + tig * 2;
            const int cl1 = cl0 + 8;
            const unsigned mk0 = *(const unsigned*)(Msh + st * 32 + kb * 8 + tig);
            const unsigned mk1 = *(const unsigned*)(Msh + st * 32 + kb * 8 + tig + 4);
            const unsigned e0 = h2ex2(pack_h2(sacc[2 * kb][0],     sacc[2 * kb][1]));
            const unsigned e1 = h2ex2(pack_h2(sacc[2 * kb][2],     sacc[2 * kb][3]));
            const unsigned e2 = h2ex2(pack_h2(sacc[2 * kb + 1][0], sacc[2 * kb + 1][1]));
            const unsigned e3 = h2ex2(pack_h2(sacc[2 * kb + 1][2], sacc[2 * kb + 1][3]));
            const unsigned a0 = hmul2u(hmul2u(e0, il0h), mk0);
            const unsigned a1 = hmul2u(hmul2u(e1, il1h), mk0);
            const unsigned a2 = hmul2u(hmul2u(e2, il0h), mk1);
            const unsigned a3 = hmul2u(hmul2u(e3, il1h), mk1);
            const int ko = kb * 8 + 2 * tig;
            // mma first (tensor pipe), stores after
#pragma unroll
            for (int nc = 0; nc < 8; nc++) {
                const uint2 bb = *(const uint2*)(vb + (nc * 8 + g) * (PH / 2) + ko);
                mma_f16(yacc[nc], a0, a1, a2, a3, bb.x, bb.y);
            }
            const long long gc0 = (long long)kc * 64 + cl0;
            const long long gc1 = (long long)kc * 64 + cl1;
            __stcs((float2*)&Sg[(long long)r0 * T_ + gc0], h2f2(a0));
            __stcs((float2*)&Sg[(long long)r1 * T_ + gc0], h2f2(a1));
            __stcs((float2*)&Sg[(long long)r0 * T_ + gc1], h2f2(a2));
            __stcs((float2*)&Sg[(long long)r1 * T_ + gc1], h2f2(a3));
        }
    }

    // write Y (half, pair-permuted within each 16 of C) for the proj GEMM
    {
#pragma unroll
        for (int nc = 0; nc < 8; nc++) {
            const int dd = nc * 8 + tig * 2;
            const int pos = h * D_ + ((dd & ~15) | (perm8((dd >> 1) & 7) << 1));
            __half* p0 = Y + (long long)(b * T_ + r0) * C_;
            __half* p1 = Y + (long long)(b * T_ + r1) * C_;
            *(__half2*)(p0 + pos) = __floats2half2_rn(yacc[nc][0], yacc[nc][1]);
            *(__half2*)(p1 + pos) = __floats2half2_rn(yacc[nc][2], yacc[nc][3]);
        }
    }
}

// ---------------------------------------------------------------------------
// Launch
// ---------------------------------------------------------------------------
extern "C" void kernel_launch(void* const* d_in, const int* in_sizes, int n_in,
                              void* d_out, int out_size)
{
    const float* x    = (const float*)d_in[0];
    const float* mask = (const float*)d_in[2];
    const float* Wq   = (const float*)d_in[3];
    const float* bq   = (const float*)d_in[4];
    const float* Wk   = (const float*)d_in[5];
    const float* bk   = (const float*)d_in[6];
    const float* Wv   = (const float*)d_in[7];
    const float* bv   = (const float*)d_in[8];
    const float* Wp   = (const float*)d_in[9];
    const float* bp   = (const float*)d_in[10];
    float* out = (float*)d_out;

    float *pq, *pk, *pvT, *py, *patt_fb, *pxr, *pwq, *pwk, *pwv, *pwp, *pmh;
    cudaGetSymbolAddress((void**)&pq, g_q);
    cudaGetSymbolAddress((void**)&pk, g_k);
    cudaGetSymbolAddress((void**)&pvT, g_vT);
    cudaGetSymbolAddress((void**)&py, g_yh);
    cudaGetSymbolAddress((void**)&patt_fb, g_att_fb);
    cudaGetSymbolAddress((void**)&pxr, g_xr);
    cudaGetSymbolAddress((void**)&pwq, g_wqr);
    cudaGetSymbolAddress((void**)&pwk, g_wkr);
    cudaGetSymbolAddress((void**)&pwv, g_wvr);
    cudaGetSymbolAddress((void**)&pwp, g_wpr);
    cudaGetSymbolAddress((void**)&pmh, g_maskh);

    float* yout;
    float* att;
    if ((long long)out_size >= Y_ELEMS + ATT_ELEMS) {
        yout = out;  att = out + Y_ELEMS;
    } else if ((long long)out_size == ATT_ELEMS) {
        yout = nullptr;  att = out;
    } else {
        yout = out;  att = patt_fb;
    }

    const int GEMM_SMEM  = 2 * 2 * 128 * PH * 2;                        // 81,920 B
    const int FLASH_SMEM = (128 + 2 * 64 + 2 * 64) * PH * 2 + 2 * 64 * 2; // 61,696 B
    cudaFuncSetAttribute(qkv_gemm,  cudaFuncAttributeMaxDynamicSharedMemorySize, GEMM_SMEM);
    cudaFuncSetAttribute(proj_gemm, cudaFuncAttributeMaxDynamicSharedMemorySize, GEMM_SMEM);
    cudaFuncSetAttribute(flash_att, cudaFuncAttributeMaxDynamicSharedMemorySize, FLASH_SMEM);

    const dim3 blk(256);

    // 0) one merged fp32 -> fp16 rounding launch (x + 4 weights + mask)
    round_half_perm_all<<<3074, 256>>>(x, Wq, Wk, Wv, Wp, mask,
                                       (__half*)pxr, (__half*)pwq, (__half*)pwk,
                                       (__half*)pwv, (__half*)pwp, (__half*)pmh);

    // 1) merged Q/K/V projections (q scaled by QSCALE; v transposed+token-perm)
    qkv_gemm<<<dim3(C_ / 128, (B_ * T_) / 128, 3), blk, GEMM_SMEM>>>(
        (const __half*)pxr, (const __half*)pwq, (const __half*)pwk, (const __half*)pwv,
        bq, bk, bv, (__half*)pq, (__half*)pk, (__half*)pvT);

    // 2) fused two-pass flash attention: att (fp32, written once) + Y (half)
    flash_att<<<dim3(1, T_ / 128, B_ * H_), blk, FLASH_SMEM>>>(
        (const __half*)pq, (const __half*)pk, (const __half*)pvT, (const __half*)pmh,
        att, (__half*)py);

    // 3) output projection (fp32 out + bias)
    if (yout)
        proj_gemm<<<dim3(C_ / 128, (B_ * T_) / 128, 1), blk, GEMM_SMEM>>>(
            (const __half*)py, (const __half*)pwp, bp, yout);
}